// round 16
// baseline (speedup 1.0000x reference)
#include <cuda_runtime.h>
#include <math.h>

#define N 96
#define NN (N*N)            // 9216
#define LATENT 256
#define OUT_DIM 4656
#define ITERS 50
#define NBLK_E 96
#define CHUNK 96
#define FXS 4194304.0f      // 2^22 fixed-point scale for encoder partials

// ---------------- static device scratch ----------------
__device__ int g_mu_fx[LATENT];                   // zero-init at load; kB re-zeroes
__device__ int g_ls_fx[LATENT];
__device__ float g_hidden[LATENT];
__device__ float g_kl;
__device__ float g_out[OUT_DIM];
__device__ float g_bce[64];
__device__ unsigned int g_bce_cnt;                // kC last-finisher counter
__device__ float g_sd[N], g_sdr[N], g_sfe[N];
__device__ unsigned int g_sfr_fx[N];              // fixed-point 2^-24 rec row sums
__device__ float g_u[2][NN];                      // u[b*N + j] = x[j][b]
__device__ unsigned long long g_root[ITERS];      // cnt<<57 | sumsq*2^30

__device__ __forceinline__ int trioff(int i) { return i * (193 - i) / 2; }

// ---------------- Kernel A: encoder matvecs -> fixed-point atomics + stats -----
__global__ void kA(const float* __restrict__ h,
                   const float* __restrict__ We11,
                   const float* __restrict__ We12,
                   const float* __restrict__ adj) {
    int bb = blockIdx.x, t = threadIdx.x;
    if (bb == 192) {                 // stats block
        if (t < N) {
            float s = 0.f;
#pragma unroll 8
            for (int j = 0; j < N; j++) s += adj[t * N + j];
            g_sfe[t] = s;
            g_sd[t] = adj[t * N + t];
        }
        return;
    }
    __shared__ float sh[CHUNK];
    int isMu = (bb < 96);
    int b = isMu ? bb : bb - 96;
    const float* W = isMu ? We11 : We12;
    int* P = isMu ? g_mu_fx : g_ls_fx;
    if (t < CHUNK) sh[t] = h[b * CHUNK + t];
    __syncthreads();
    float s = 0.f;
    long base = (long)b * CHUNK * LATENT + t;
#pragma unroll 16
    for (int k = 0; k < CHUNK; k++)
        s = fmaf(sh[k], W[base + (long)k * LATENT], s);
    // deterministic (integer) accumulation across the 96 split-K blocks
    atomicAdd(&P[t], __float2int_rn(s * FXS));
}

// ---------------- Kernel B: reparam, KL, hidden; zero barrier state ------------
__global__ void kB(const float* __restrict__ eps,
                   const float* __restrict__ be11,
                   const float* __restrict__ be12,
                   const float* __restrict__ Wd1,
                   const float* __restrict__ bd1) {
    int t = threadIdx.x;
    if (t < ITERS) g_root[t] = 0ull;
    if (t < N) g_sfr_fx[t] = 0u;

    float mu = be11[t] + (float)g_mu_fx[t] * (1.0f / FXS);
    float ls = be12[t] + (float)g_ls_fx[t] * (1.0f / FXS);
    g_mu_fx[t] = 0;      // reset for next graph replay
    g_ls_fx[t] = 0;
    float z = fmaf(eps[t], expf(0.5f * ls), mu);
    float klp = 1.0f + ls - mu * mu - expf(ls);

    __shared__ float sz[LATENT];
    __shared__ float sred[8];
    sz[t] = z;
#pragma unroll
    for (int off = 16; off; off >>= 1) klp += __shfl_xor_sync(0xffffffffu, klp, off);
    if ((t & 31) == 0) sred[t >> 5] = klp;
    __syncthreads();
    if (t == 0) {
        float s = 0.f;
#pragma unroll
        for (int w = 0; w < 8; w++) s += sred[w];
        g_kl = -0.5f * s / (float)NN;
    }
    float acc = bd1[t];
#pragma unroll 8
    for (int l = 0; l < LATENT; l++) acc = fmaf(sz[l], Wd1[l * LATENT + t], acc);
    g_hidden[t] = fmaxf(acc, 0.f);
}

// ---- Kernel C: output layer, sigmoid, BCE, recon stats, last-block loss -------
__global__ void kC(const float* __restrict__ Wd2,
                   const float* __restrict__ bd2,
                   const float* __restrict__ adj,
                   float* __restrict__ d_out, int write_loss) {
    __shared__ float sH[LATENT];
    __shared__ float sred[4];
    int t = threadIdx.x;
    sH[t] = g_hidden[t];
    sH[t + 128] = g_hidden[t + 128];
    __syncthreads();
    int o = blockIdx.x * 128 + t;
    float term = 0.f;
    if (o < OUT_DIM) {
        float y = bd2[o];
#pragma unroll 8
        for (int l = 0; l < LATENT; l++) y = fmaf(sH[l], Wd2[l * OUT_DIM + o], y);
        float ov = 1.f / (1.f + expf(-y));
        g_out[o] = ov;
        int i = (int)((193.0f - sqrtf(37249.0f - 8.0f * (float)o)) * 0.5f);
        if (i < 0) i = 0;
        if (i > 95) i = 95;
        while (i < 95 && trioff(i + 1) <= o) i++;
        while (i > 0 && trioff(i) > o) i--;
        int j = o - trioff(i) + i;
        unsigned q = (unsigned)__float2uint_rn(ov * 16777216.f);
        atomicAdd(&g_sfr_fx[i], q);
        if (j != i) atomicAdd(&g_sfr_fx[j], q);
        else g_sdr[i] = ov;
        float inp = adj[i * N + j];
        float li = fmaxf(logf(inp), -100.f);
        float l1 = fmaxf(log1pf(-inp), -100.f);
        term = fmaf(ov, li, (1.f - ov) * l1);
    }
#pragma unroll
    for (int off = 16; off; off >>= 1) term += __shfl_xor_sync(0xffffffffu, term, off);
    if ((t & 31) == 0) sred[t >> 5] = term;
    __syncthreads();
    if (t == 0) {
        g_bce[blockIdx.x] = sred[0] + sred[1] + sred[2] + sred[3];
        if (write_loss) {
            __threadfence();                       // my g_bce store visible first
            unsigned prev = atomicAdd(&g_bce_cnt, 1u);
            if (prev == 36u) {                     // last finisher: all 37 visible
                __threadfence();
                float s = 0.f;
#pragma unroll
                for (int b = 0; b < 37; b++) s += g_bce[b];
                d_out[0] = -s / (float)OUT_DIM + g_kl;
                g_bce_cnt = 0u;                    // reset for next graph replay
            }
        }
    }
}

// ---- Kernel E: R12-proven persistent MPM (flat t0-RED + all-thread poll) ------
__global__ void __launch_bounds__(384) kE(const float* __restrict__ adj,
                                          float* __restrict__ d_out, int base) {
    __shared__ float sU[NN];        // 36KB staged u
    __shared__ float ssd[N], ssdr[N];
    __shared__ float sMp[4][N];
    __shared__ float sCp[4][N];
    __shared__ float sM[N];
    __shared__ float sred[3];

    int t = threadIdx.x, lane = t & 31, warp = t >> 5;   // 12 warps
    int rowg = warp % 3, quarter = warp / 3;
    int row = rowg * 32 + lane;
    int b0 = quarter * 24;
    int a = blockIdx.x;

    if (t < N) { ssd[t] = g_sd[t]; ssdr[t] = g_sdr[t]; }
    __syncthreads();

    // ---- prologue: rB (B' row a), rA (A' row 'row'), rSd in registers ----
    float rB[24], rA[24];
    float sdr_a = ssdr[a];
#pragma unroll
    for (int q = 0; q < 24; q++) {
        int b = b0 + q;
        rA[q] = (row != b) ? adj[row * N + b] * ssd[row] * ssd[b] : 0.f;
        int lo = min(a, b), hi = max(a, b);
        float rec = g_out[trioff(lo) + hi - lo];
        rB[q] = (a != b) ? rec * sdr_a * ssdr[b] : 0.f;
    }
    float rSd = 0.f;
    if (quarter == 0) {
        float sfr_a = (float)g_sfr_fx[a] * (1.f / 16777216.f);
        rSd = ssd[row] * sdr_a / (fabsf(g_sfe[row] - sfr_a) + 1.0f);
    }

    float rinv = 1.0f;     // ||u0|| = 1
    float vlast = 0.f;

    for (int k = 0; k < ITERS; k++) {
        const float* ur = g_u[k & 1];
        float* uw = g_u[(k + 1) & 1];

        float uold;
        float m0 = 0.f, m1 = 0.f, m2 = 0.f, m3 = 0.f;
        if (k == 0) {
            const float c = 1.0f / 96.0f;    // u0 uniform
            uold = c;
#pragma unroll
            for (int q = 0; q < 24; q += 4) {
                m0 = fmaxf(m0, rB[q] * c);
                m1 = fmaxf(m1, rB[q + 1] * c);
                m2 = fmaxf(m2, rB[q + 2] * c);
                m3 = fmaxf(m3, rB[q + 3] * c);
            }
        } else {
            // ---- bulk-coalesced stage of full u into smem ----
            const float4* src = (const float4*)ur;
            float4* dst = (float4*)sU;
#pragma unroll
            for (int w = 0; w < 6; w++)
                dst[w * 384 + t] = __ldcg(&src[w * 384 + t]);
            __syncthreads();
            uold = (quarter == 0) ? sU[a * N + row] : 0.f;
#pragma unroll
            for (int q = 0; q < 24; q += 4) {
                m0 = fmaxf(m0, rB[q]     * sU[(b0 + q)     * N + row]);
                m1 = fmaxf(m1, rB[q + 1] * sU[(b0 + q + 1) * N + row]);
                m2 = fmaxf(m2, rB[q + 2] * sU[(b0 + q + 2) * N + row]);
                m3 = fmaxf(m3, rB[q + 3] * sU[(b0 + q + 3) * N + row]);
            }
        }
        sMp[quarter][row] = fmaxf(fmaxf(m0, m1), fmaxf(m2, m3));
        __syncthreads();

        if (t < N) sM[t] = fmaxf(fmaxf(sMp[0][t], sMp[1][t]),
                                 fmaxf(sMp[2][t], sMp[3][t]));
        __syncthreads();

        // ---- update partial: sum over this quarter's 24 j values ----
        float c0 = 0.f, c1 = 0.f, c2 = 0.f, c3 = 0.f;
#pragma unroll
        for (int q = 0; q < 24; q += 4) {
            c0 = fmaf(rA[q],     sM[b0 + q],     c0);
            c1 = fmaf(rA[q + 1], sM[b0 + q + 1], c1);
            c2 = fmaf(rA[q + 2], sM[b0 + q + 2], c2);
            c3 = fmaf(rA[q + 3], sM[b0 + q + 3], c3);
        }
        sCp[quarter][row] = (c0 + c1) + (c2 + c3);
        __syncthreads();

        // ---- finalize column a; store; overlap norm-shfl with store drain ----
        if (quarter == 0) {
            float acc = (sCp[0][row] + sCp[1][row]) + (sCp[2][row] + sCp[3][row]);
            float v = rinv * fmaf(uold, rSd, acc);
            if (k < ITERS - 1) __stcg(&uw[a * N + row], v);
            vlast = v;
            float sq = v * v;
#pragma unroll
            for (int off = 16; off; off >>= 1)
                sq += __shfl_xor_sync(0xffffffffu, sq, off);   // hides store drain
            if (lane == 0) sred[rowg] = sq;
            __threadfence();   // per-storer drain (PROVEN required: R6 vs R7)
        }
        __syncthreads();

        // ---- flat barrier: t0 posts ONE packed RED; ALL threads poll root ----
        if (t == 0) {
            float s = sred[0] + sred[1] + sred[2];
            atomicAdd(&g_root[k], (1ull << 57)
                | (unsigned long long)__float2ll_rn(s * 1073741824.0f));  // RED
        }
        unsigned long long rw;
        do {
            asm volatile("ld.volatile.global.u64 %0, [%1];"
                         : "=l"(rw) : "l"(&g_root[k]) : "memory");
        } while ((rw >> 57) != (unsigned long long)NBLK_E);
        rinv = rsqrtf((float)(long long)(rw & ((1ull << 57) - 1ull))
                      * (1.0f / 1073741824.0f));
    }

    // ---- output: rinv = 1/||u_50||; exact final normalization ----
    if (quarter == 0) {
        d_out[base + row * N + a] = vlast * rinv;
    }
}

// ---------------- launch ----------------
extern "C" void kernel_launch(void* const* d_in, const int* in_sizes, int n_in,
                              void* d_out, int out_size) {
    const float* feats = (const float*)d_in[0];
    const float* adj   = (const float*)d_in[1];
    const float* eps   = (const float*)d_in[2];
    const float* We11  = (const float*)d_in[3];
    const float* be11  = (const float*)d_in[4];
    const float* We12  = (const float*)d_in[5];
    const float* be12  = (const float*)d_in[6];
    const float* Wd1   = (const float*)d_in[7];
    const float* bd1   = (const float*)d_in[8];
    const float* Wd2   = (const float*)d_in[9];
    const float* bd2   = (const float*)d_in[10];
    float* out = (float*)d_out;

    int has_loss = (out_size > NN) ? 1 : 0;
    int base = has_loss ? 1 : 0;

    kA<<<193, 256>>>(feats, We11, We12, adj);
    kB<<<1, 256>>>(eps, be11, be12, Wd1, bd1);
    kC<<<37, 128>>>(Wd2, bd2, adj, out, has_loss);
    kE<<<NBLK_E, 384>>>(adj, out, base);     // 4th launch -> ncu capture slot
}

// round 17
// speedup vs baseline: 1.0783x; 1.0783x over previous
#include <cuda_runtime.h>
#include <math.h>

#define N 96
#define NN (N*N)            // 9216
#define LATENT 256
#define OUT_DIM 4656
#define ITERS 50
#define NBLK_E 96
#define CHUNK 96

// ---------------- static device scratch ----------------
__device__ float g_part_mu[96 * LATENT];
__device__ float g_part_ls[96 * LATENT];
__device__ float g_hidden[LATENT];
__device__ float g_kl;
__device__ float g_out[OUT_DIM];
__device__ float g_bce[64];
__device__ unsigned int g_bce_cnt;                // kC last-finisher counter (0-init)
__device__ float g_sd[N], g_sdr[N], g_sfe[N];
__device__ unsigned int g_sfr_fx[N];              // fixed-point 2^-24 rec row sums
__device__ float g_u[2][NN];                      // u[b*N + j] = x[j][b]
__device__ unsigned long long g_root[ITERS];      // cnt<<57 | sumsq*2^30

__device__ __forceinline__ int trioff(int i) { return i * (193 - i) / 2; }

// ---------------- Kernel A: encoder matvec partials + adj stats ----------------
__global__ void kA(const float* __restrict__ h,
                   const float* __restrict__ We11,
                   const float* __restrict__ We12,
                   const float* __restrict__ adj) {
    int bb = blockIdx.x, t = threadIdx.x;
    if (bb == 192) {                 // stats block
        if (t < N) {
            float s = 0.f;
#pragma unroll 4
            for (int j = 0; j < N; j++) s += adj[t * N + j];
            g_sfe[t] = s;
            g_sd[t] = adj[t * N + t];
        }
        return;
    }
    __shared__ float sh[CHUNK];
    int isMu = (bb < 96);
    int b = isMu ? bb : bb - 96;
    const float* W = isMu ? We11 : We12;
    float* P = isMu ? g_part_mu : g_part_ls;
    if (t < CHUNK) sh[t] = h[b * CHUNK + t];
    __syncthreads();
    float s = 0.f;
    long base = (long)b * CHUNK * LATENT + t;
#pragma unroll 8
    for (int k = 0; k < CHUNK; k++)
        s = fmaf(sh[k], W[base + (long)k * LATENT], s);
    P[b * LATENT + t] = s;
}

// ---------------- Kernel B: reduce, reparam, KL, hidden; zero barrier state ----
__global__ void kB(const float* __restrict__ eps,
                   const float* __restrict__ be11,
                   const float* __restrict__ be12,
                   const float* __restrict__ Wd1,
                   const float* __restrict__ bd1) {
    int t = threadIdx.x;
    if (t < ITERS) g_root[t] = 0ull;
    if (t < N) g_sfr_fx[t] = 0u;

    float mu = be11[t], ls = be12[t];
#pragma unroll 4
    for (int b = 0; b < 96; b++) {
        mu += g_part_mu[b * LATENT + t];
        ls += g_part_ls[b * LATENT + t];
    }
    float z = fmaf(eps[t], expf(0.5f * ls), mu);
    float klp = 1.0f + ls - mu * mu - expf(ls);

    __shared__ float sz[LATENT];
    __shared__ float sred[8];
    sz[t] = z;
#pragma unroll
    for (int off = 16; off; off >>= 1) klp += __shfl_xor_sync(0xffffffffu, klp, off);
    if ((t & 31) == 0) sred[t >> 5] = klp;
    __syncthreads();
    if (t == 0) {
        float s = 0.f;
#pragma unroll
        for (int w = 0; w < 8; w++) s += sred[w];
        g_kl = -0.5f * s / (float)NN;
    }
    float acc = bd1[t];
#pragma unroll 16
    for (int l = 0; l < LATENT; l++) acc = fmaf(sz[l], Wd1[l * LATENT + t], acc);
    g_hidden[t] = fmaxf(acc, 0.f);
}

// ---- Kernel C: output layer, sigmoid, BCE, recon stats, last-block loss -------
__global__ void kC(const float* __restrict__ Wd2,
                   const float* __restrict__ bd2,
                   const float* __restrict__ adj,
                   float* __restrict__ d_out, int write_loss) {
    __shared__ float sH[LATENT];
    __shared__ float sred[4];
    int t = threadIdx.x;
    sH[t] = g_hidden[t];
    sH[t + 128] = g_hidden[t + 128];
    __syncthreads();
    int o = blockIdx.x * 128 + t;
    float term = 0.f;
    if (o < OUT_DIM) {
        float y = bd2[o];
#pragma unroll 8
        for (int l = 0; l < LATENT; l++) y = fmaf(sH[l], Wd2[l * OUT_DIM + o], y);
        float ov = 1.f / (1.f + expf(-y));
        g_out[o] = ov;
        int i = (int)((193.0f - sqrtf(37249.0f - 8.0f * (float)o)) * 0.5f);
        if (i < 0) i = 0;
        if (i > 95) i = 95;
        while (i < 95 && trioff(i + 1) <= o) i++;
        while (i > 0 && trioff(i) > o) i--;
        int j = o - trioff(i) + i;
        unsigned q = (unsigned)__float2uint_rn(ov * 16777216.f);
        atomicAdd(&g_sfr_fx[i], q);
        if (j != i) atomicAdd(&g_sfr_fx[j], q);
        else g_sdr[i] = ov;
        float inp = adj[i * N + j];
        float li = fmaxf(logf(inp), -100.f);
        float l1 = fmaxf(log1pf(-inp), -100.f);
        term = fmaf(ov, li, (1.f - ov) * l1);
    }
#pragma unroll
    for (int off = 16; off; off >>= 1) term += __shfl_xor_sync(0xffffffffu, term, off);
    if ((t & 31) == 0) sred[t >> 5] = term;
    __syncthreads();
    if (t == 0) {
        g_bce[blockIdx.x] = sred[0] + sred[1] + sred[2] + sred[3];
        if (write_loss) {
            __threadfence();                       // my g_bce store visible first
            unsigned prev = atomicAdd(&g_bce_cnt, 1u);
            if (prev == 36u) {                     // last finisher: all 37 visible
                __threadfence();
                float s = 0.f;
#pragma unroll
                for (int b = 0; b < 37; b++) s += g_bce[b];
                d_out[0] = -s / (float)OUT_DIM + g_kl;
                g_bce_cnt = 0u;                    // reset for next graph replay
            }
        }
    }
}

// ---- Kernel E: R12-proven persistent MPM (flat t0-RED + all-thread poll) ------
__global__ void __launch_bounds__(384) kE(const float* __restrict__ adj,
                                          float* __restrict__ d_out, int base) {
    __shared__ float sU[NN];        // 36KB staged u
    __shared__ float ssd[N], ssdr[N];
    __shared__ float sMp[4][N];
    __shared__ float sCp[4][N];
    __shared__ float sM[N];
    __shared__ float sred[3];

    int t = threadIdx.x, lane = t & 31, warp = t >> 5;   // 12 warps
    int rowg = warp % 3, quarter = warp / 3;
    int row = rowg * 32 + lane;
    int b0 = quarter * 24;
    int a = blockIdx.x;

    if (t < N) { ssd[t] = g_sd[t]; ssdr[t] = g_sdr[t]; }
    __syncthreads();

    // ---- prologue: rB (B' row a), rA (A' row 'row'), rSd in registers ----
    float rB[24], rA[24];
    float sdr_a = ssdr[a];
#pragma unroll
    for (int q = 0; q < 24; q++) {
        int b = b0 + q;
        rA[q] = (row != b) ? adj[row * N + b] * ssd[row] * ssd[b] : 0.f;
        int lo = min(a, b), hi = max(a, b);
        float rec = g_out[trioff(lo) + hi - lo];
        rB[q] = (a != b) ? rec * sdr_a * ssdr[b] : 0.f;
    }
    float rSd = 0.f;
    if (quarter == 0) {
        float sfr_a = (float)g_sfr_fx[a] * (1.f / 16777216.f);
        rSd = ssd[row] * sdr_a / (fabsf(g_sfe[row] - sfr_a) + 1.0f);
    }

    float rinv = 1.0f;     // ||u0|| = 1
    float vlast = 0.f;

    for (int k = 0; k < ITERS; k++) {
        const float* ur = g_u[k & 1];
        float* uw = g_u[(k + 1) & 1];

        float uold;
        float m0 = 0.f, m1 = 0.f, m2 = 0.f, m3 = 0.f;
        if (k == 0) {
            const float c = 1.0f / 96.0f;    // u0 uniform
            uold = c;
#pragma unroll
            for (int q = 0; q < 24; q += 4) {
                m0 = fmaxf(m0, rB[q] * c);
                m1 = fmaxf(m1, rB[q + 1] * c);
                m2 = fmaxf(m2, rB[q + 2] * c);
                m3 = fmaxf(m3, rB[q + 3] * c);
            }
        } else {
            // ---- bulk-coalesced stage of full u into smem ----
            const float4* src = (const float4*)ur;
            float4* dst = (float4*)sU;
#pragma unroll
            for (int w = 0; w < 6; w++)
                dst[w * 384 + t] = __ldcg(&src[w * 384 + t]);
            __syncthreads();
            uold = (quarter == 0) ? sU[a * N + row] : 0.f;
#pragma unroll
            for (int q = 0; q < 24; q += 4) {
                m0 = fmaxf(m0, rB[q]     * sU[(b0 + q)     * N + row]);
                m1 = fmaxf(m1, rB[q + 1] * sU[(b0 + q + 1) * N + row]);
                m2 = fmaxf(m2, rB[q + 2] * sU[(b0 + q + 2) * N + row]);
                m3 = fmaxf(m3, rB[q + 3] * sU[(b0 + q + 3) * N + row]);
            }
        }
        sMp[quarter][row] = fmaxf(fmaxf(m0, m1), fmaxf(m2, m3));
        __syncthreads();

        if (t < N) sM[t] = fmaxf(fmaxf(sMp[0][t], sMp[1][t]),
                                 fmaxf(sMp[2][t], sMp[3][t]));
        __syncthreads();

        // ---- update partial: sum over this quarter's 24 j values ----
        float c0 = 0.f, c1 = 0.f, c2 = 0.f, c3 = 0.f;
#pragma unroll
        for (int q = 0; q < 24; q += 4) {
            c0 = fmaf(rA[q],     sM[b0 + q],     c0);
            c1 = fmaf(rA[q + 1], sM[b0 + q + 1], c1);
            c2 = fmaf(rA[q + 2], sM[b0 + q + 2], c2);
            c3 = fmaf(rA[q + 3], sM[b0 + q + 3], c3);
        }
        sCp[quarter][row] = (c0 + c1) + (c2 + c3);
        __syncthreads();

        // ---- finalize column a; store; overlap norm-shfl with store drain ----
        if (quarter == 0) {
            float acc = (sCp[0][row] + sCp[1][row]) + (sCp[2][row] + sCp[3][row]);
            float v = rinv * fmaf(uold, rSd, acc);
            if (k < ITERS - 1) __stcg(&uw[a * N + row], v);
            vlast = v;
            float sq = v * v;
#pragma unroll
            for (int off = 16; off; off >>= 1)
                sq += __shfl_xor_sync(0xffffffffu, sq, off);   // hides store drain
            if (lane == 0) sred[rowg] = sq;
            __threadfence();   // per-storer drain (PROVEN required: R6 vs R7)
        }
        __syncthreads();

        // ---- flat barrier: t0 posts ONE packed RED; ALL threads poll root ----
        if (t == 0) {
            float s = sred[0] + sred[1] + sred[2];
            atomicAdd(&g_root[k], (1ull << 57)
                | (unsigned long long)__float2ll_rn(s * 1073741824.0f));  // RED
        }
        unsigned long long rw;
        do {
            asm volatile("ld.volatile.global.u64 %0, [%1];"
                         : "=l"(rw) : "l"(&g_root[k]) : "memory");
        } while ((rw >> 57) != (unsigned long long)NBLK_E);
        rinv = rsqrtf((float)(long long)(rw & ((1ull << 57) - 1ull))
                      * (1.0f / 1073741824.0f));
    }

    // ---- output: rinv = 1/||u_50||; exact final normalization ----
    if (quarter == 0) {
        d_out[base + row * N + a] = vlast * rinv;
    }
}

// ---------------- launch ----------------
extern "C" void kernel_launch(void* const* d_in, const int* in_sizes, int n_in,
                              void* d_out, int out_size) {
    const float* feats = (const float*)d_in[0];
    const float* adj   = (const float*)d_in[1];
    const float* eps   = (const float*)d_in[2];
    const float* We11  = (const float*)d_in[3];
    const float* be11  = (const float*)d_in[4];
    const float* We12  = (const float*)d_in[5];
    const float* be12  = (const float*)d_in[6];
    const float* Wd1   = (const float*)d_in[7];
    const float* bd1   = (const float*)d_in[8];
    const float* Wd2   = (const float*)d_in[9];
    const float* bd2   = (const float*)d_in[10];
    float* out = (float*)d_out;

    int has_loss = (out_size > NN) ? 1 : 0;
    int base = has_loss ? 1 : 0;

    kA<<<193, 256>>>(feats, We11, We12, adj);
    kB<<<1, 256>>>(eps, be11, be12, Wd1, bd1);
    kC<<<37, 128>>>(Wd2, bd2, adj, out, has_loss);
    kE<<<NBLK_E, 384>>>(adj, out, base);     // 4th launch -> ncu capture slot
}